// round 5
// baseline (speedup 1.0000x reference)
#include <cuda_runtime.h>
#include <math.h>

#define BB     64
#define EMB    1024
#define CDEC   2048     // WIDTH*MODES*2
#define WID    64
#define MODES  16
#define JJ     32       // 2*MODES
#define LL     8192
#define LOUT   8190
#define N1     128

// device scratch (no allocations allowed)
__device__ float g_M[BB * JJ * WID];   // [b][j][w] scaled mode coeffs
__device__ float g_G[BB * JJ * N1];    // [b][j][n] = M[b] @ w1
__device__ float g_C[LOUT * JJ];       // [t][j] trig table (cos at 2k, sin at 2k+1)

// ---------------------------------------------------------------------------
// K1: h = token @ w_dec + b_dec, scaled directly into M[b][j][w].
// column c = w*32 + j  (j = 2k + reim). Block: 128 c-columns x 8 batches.
// ---------------------------------------------------------------------------
__global__ void __launch_bounds__(128) k_decode(
    const float* __restrict__ token, const float* __restrict__ w_dec,
    const float* __restrict__ b_dec)
{
    __shared__ float tok[8 * EMB];   // [p][bb] layout: tok[p*8+bb], 32KB
    const int tx = threadIdx.x;
    const int b0 = blockIdx.y * 8;
    const int c  = blockIdx.x * 128 + tx;

    // coalesced global read, transposed smem write ([p][bb])
    for (int i = tx; i < 8 * EMB; i += 128) {
        int bb = i >> 10, p = i & 1023;
        tok[p * 8 + bb] = token[(b0 + bb) * EMB + p];
    }
    __syncthreads();

    float acc0 = 0.f, acc1 = 0.f, acc2 = 0.f, acc3 = 0.f;
    float acc4 = 0.f, acc5 = 0.f, acc6 = 0.f, acc7 = 0.f;
#pragma unroll 4
    for (int p = 0; p < EMB; p++) {
        float wv = w_dec[p * CDEC + c];
        float4 t0 = *reinterpret_cast<const float4*>(&tok[p * 8]);
        float4 t1 = *reinterpret_cast<const float4*>(&tok[p * 8 + 4]);
        acc0 = fmaf(t0.x, wv, acc0); acc1 = fmaf(t0.y, wv, acc1);
        acc2 = fmaf(t0.z, wv, acc2); acc3 = fmaf(t0.w, wv, acc3);
        acc4 = fmaf(t1.x, wv, acc4); acc5 = fmaf(t1.y, wv, acc5);
        acc6 = fmaf(t1.z, wv, acc6); acc7 = fmaf(t1.w, wv, acc7);
    }
    float bd = b_dec[c];
    int w = c >> 5, j = c & 31;
    // irfft coefficients: DC cos = 1/L, Im(X0) ignored (sin(0)=0 anyway -> 0),
    // k>=1: cos coeff 2*Re/L, sin coeff -2*Im/L
    float sc;
    if (j == 0)      sc = 1.0f / (float)LL;
    else if (j == 1) sc = 0.0f;
    else             sc = (j & 1) ? (-2.0f / (float)LL) : (2.0f / (float)LL);

    float a[8] = {acc0, acc1, acc2, acc3, acc4, acc5, acc6, acc7};
#pragma unroll
    for (int bb = 0; bb < 8; bb++)
        g_M[(b0 + bb) * (JJ * WID) + j * WID + w] = sc * (a[bb] + bd);
}

// ---------------------------------------------------------------------------
// K2: G[b] = M[b] (32x64) @ w1 (64x128). One block per b.
// ---------------------------------------------------------------------------
__global__ void __launch_bounds__(256) k_fusemat(const float* __restrict__ w1)
{
    __shared__ float Ms[JJ * WID];    // 8KB
    __shared__ float W1s[WID * N1];   // 32KB
    const int tid = threadIdx.x;
    const int b = blockIdx.x;
    for (int i = tid; i < JJ * WID; i += 256) Ms[i] = g_M[b * JJ * WID + i];
    for (int i = tid; i < WID * N1; i += 256) W1s[i] = w1[i];
    __syncthreads();
    for (int idx = tid; idx < JJ * N1; idx += 256) {
        int j = idx >> 7, n = idx & 127;
        float acc = 0.f;
#pragma unroll 8
        for (int p = 0; p < WID; p++)
            acc = fmaf(Ms[j * WID + p], W1s[p * N1 + n], acc);
        g_G[b * JJ * N1 + idx] = acc;
    }
}

// ---------------------------------------------------------------------------
// K3: trig table. Exact integer phase reduction since L = 8192 = 2^13.
// ---------------------------------------------------------------------------
__global__ void __launch_bounds__(256) k_trig()
{
    int idx = blockIdx.x * 256 + threadIdx.x;
    if (idx >= LOUT * MODES) return;
    int t = idx >> 4, k = idx & 15;
    int m = (t * k) & (LL - 1);
    float ang = (float)m * 7.6699039394282058e-4f;  // 2*pi/8192
    float s, c;
    sincosf(ang, &s, &c);
    g_C[t * JJ + 2 * k]     = c;
    g_C[t * JJ + 2 * k + 1] = s;
}

// ---------------------------------------------------------------------------
// K4: fused main: preact = C[t] @ G[b] + b1 -> gelu -> dot(w2) + b2.
// Block 256 = 8 warps, one warp per t. Each lane owns 4 of 128 fc1 columns.
// ---------------------------------------------------------------------------
__global__ void __launch_bounds__(256) k_main(
    const float* __restrict__ b1, const float* __restrict__ w2,
    const float* __restrict__ b2, float* __restrict__ out)
{
    __shared__ float4 Gs[JJ * 32];   // 32 rows x 128 cols as float4, 16KB
    const int tid = threadIdx.x;
    const int b = blockIdx.y;
    const float4* Gg = reinterpret_cast<const float4*>(g_G + b * JJ * N1);
    for (int i = tid; i < JJ * 32; i += 256) Gs[i] = Gg[i];
    __syncthreads();

    const int lane = tid & 31, warp = tid >> 5;
    const float4 b1v = reinterpret_cast<const float4*>(b1)[lane];
    const float4 w2v = reinterpret_cast<const float4*>(w2)[lane];
    const float bias2 = b2[0];

    const int tstep = gridDim.x * 8;
    for (int t = blockIdx.x * 8 + warp; t < LOUT; t += tstep) {
        float cval = g_C[t * JJ + lane];   // lane j holds C[t][j]
        float4 acc = b1v;
#pragma unroll
        for (int j = 0; j < JJ; j++) {
            float cj = __shfl_sync(0xffffffffu, cval, j);
            float4 g = Gs[j * 32 + lane];
            acc.x = fmaf(cj, g.x, acc.x);
            acc.y = fmaf(cj, g.y, acc.y);
            acc.z = fmaf(cj, g.z, acc.z);
            acc.w = fmaf(cj, g.w, acc.w);
        }
        // exact gelu (approximate=False): 0.5*x*(1+erf(x/sqrt(2)))
        float h0 = 0.5f * acc.x * (1.f + erff(acc.x * 0.70710678118654752f));
        float h1 = 0.5f * acc.y * (1.f + erff(acc.y * 0.70710678118654752f));
        float h2 = 0.5f * acc.z * (1.f + erff(acc.z * 0.70710678118654752f));
        float h3 = 0.5f * acc.w * (1.f + erff(acc.w * 0.70710678118654752f));
        float part = fmaf(h0, w2v.x, fmaf(h1, w2v.y, fmaf(h2, w2v.z, h3 * w2v.w)));
#pragma unroll
        for (int off = 16; off; off >>= 1)
            part += __shfl_xor_sync(0xffffffffu, part, off);
        if (lane == 0) out[b * LOUT + t] = part + bias2;
    }
}

// ---------------------------------------------------------------------------
extern "C" void kernel_launch(void* const* d_in, const int* in_sizes, int n_in,
                              void* d_out, int out_size)
{
    // input order: token, [x_len scalar], w_dec, b_dec, w1, b1, w2, b2
    int i = 1;
    if (n_in >= 8 && in_sizes[1] == 1) i = 2;  // skip x_len if present
    const float* token = (const float*)d_in[0];
    const float* w_dec = (const float*)d_in[i];
    const float* b_dec = (const float*)d_in[i + 1];
    const float* w1    = (const float*)d_in[i + 2];
    const float* b1    = (const float*)d_in[i + 3];
    const float* w2    = (const float*)d_in[i + 4];
    const float* b2    = (const float*)d_in[i + 5];
    float* out = (float*)d_out;

    k_decode<<<dim3(CDEC / 128, BB / 8), 128>>>(token, w_dec, b_dec);
    k_fusemat<<<BB, 256>>>(w1);
    k_trig<<<(LOUT * MODES + 255) / 256, 256>>>();
    k_main<<<dim3(24, BB), 256>>>(b1, w2, b2, out);
}

// round 7
// speedup vs baseline: 2.1828x; 2.1828x over previous
#include <cuda_runtime.h>
#include <math.h>

#define BB     64
#define EMB    1024
#define CDEC   2048     // WIDTH*MODES*2
#define WID    64
#define MODES  16
#define JJ     32       // 2*MODES
#define LL     8192
#define LOUT   8190
#define N1     128
#define TQ     2048     // base t range [0, 2048]; mirrors cover the rest

// device scratch (no allocations allowed)
__device__ float g_M[BB * JJ * WID];       // [b][j][w] scaled mode coeffs
__device__ float g_G[BB * JJ * N1];        // [b][j][n] = M[b] @ w1
__device__ float g_C[(TQ + 2) * JJ];       // [t][j] trig for t in [0,2048]

// ---------------------------------------------------------------------------
// float4 helpers
// ---------------------------------------------------------------------------
__device__ __forceinline__ float4 f4add(float4 a, float4 b) {
    return make_float4(a.x + b.x, a.y + b.y, a.z + b.z, a.w + b.w);
}
__device__ __forceinline__ float4 f4sub(float4 a, float4 b) {
    return make_float4(a.x - b.x, a.y - b.y, a.z - b.z, a.w - b.w);
}
__device__ __forceinline__ float4 f4fma(float s, float4 a, float4 acc) {
    return make_float4(fmaf(s, a.x, acc.x), fmaf(s, a.y, acc.y),
                       fmaf(s, a.z, acc.z), fmaf(s, a.w, acc.w));
}
__device__ __forceinline__ float gelu1(float x) {
    return 0.5f * x * (1.f + erff(x * 0.70710678118654752f));
}

// ---------------------------------------------------------------------------
// K1: h = token @ w_dec + b_dec, scaled directly into M[b][j][w].
// ---------------------------------------------------------------------------
__global__ void __launch_bounds__(128) k_decode(
    const float* __restrict__ token, const float* __restrict__ w_dec,
    const float* __restrict__ b_dec)
{
    __shared__ float tok[8 * EMB];   // [p][bb], 32KB
    const int tx = threadIdx.x;
    const int b0 = blockIdx.y * 8;
    const int c  = blockIdx.x * 128 + tx;

    for (int i = tx; i < 8 * EMB; i += 128) {
        int bb = i >> 10, p = i & 1023;
        tok[p * 8 + bb] = token[(b0 + bb) * EMB + p];
    }
    __syncthreads();

    float acc0 = 0.f, acc1 = 0.f, acc2 = 0.f, acc3 = 0.f;
    float acc4 = 0.f, acc5 = 0.f, acc6 = 0.f, acc7 = 0.f;
#pragma unroll 4
    for (int p = 0; p < EMB; p++) {
        float wv = w_dec[p * CDEC + c];
        float4 t0 = *reinterpret_cast<const float4*>(&tok[p * 8]);
        float4 t1 = *reinterpret_cast<const float4*>(&tok[p * 8 + 4]);
        acc0 = fmaf(t0.x, wv, acc0); acc1 = fmaf(t0.y, wv, acc1);
        acc2 = fmaf(t0.z, wv, acc2); acc3 = fmaf(t0.w, wv, acc3);
        acc4 = fmaf(t1.x, wv, acc4); acc5 = fmaf(t1.y, wv, acc5);
        acc6 = fmaf(t1.z, wv, acc6); acc7 = fmaf(t1.w, wv, acc7);
    }
    float bd = b_dec[c];
    int w = c >> 5, j = c & 31;
    // irfft coefficients: DC cos = 1/L, Im(X0) ignored; k>=1: 2*Re/L, -2*Im/L
    float sc;
    if (j == 0)      sc = 1.0f / (float)LL;
    else if (j == 1) sc = 0.0f;
    else             sc = (j & 1) ? (-2.0f / (float)LL) : (2.0f / (float)LL);

    float a[8] = {acc0, acc1, acc2, acc3, acc4, acc5, acc6, acc7};
#pragma unroll
    for (int bb = 0; bb < 8; bb++)
        g_M[(b0 + bb) * (JJ * WID) + j * WID + w] = sc * (a[bb] + bd);
}

// ---------------------------------------------------------------------------
// K2: G[b] = M[b] (32x64) @ w1 (64x128). One block per b.
// ---------------------------------------------------------------------------
__global__ void __launch_bounds__(256) k_fusemat(const float* __restrict__ w1)
{
    __shared__ float Ms[JJ * WID];
    __shared__ float W1s[WID * N1];
    const int tid = threadIdx.x;
    const int b = blockIdx.x;
    for (int i = tid; i < JJ * WID; i += 256) Ms[i] = g_M[b * JJ * WID + i];
    for (int i = tid; i < WID * N1; i += 256) W1s[i] = w1[i];
    __syncthreads();
    for (int idx = tid; idx < JJ * N1; idx += 256) {
        int j = idx >> 7, n = idx & 127;
        float acc = 0.f;
#pragma unroll 8
        for (int p = 0; p < WID; p++)
            acc = fmaf(Ms[j * WID + p], W1s[p * N1 + n], acc);
        g_G[b * JJ * N1 + idx] = acc;
    }
}

// ---------------------------------------------------------------------------
// K3: trig table for base t in [0, 2048] only (symmetry covers the rest).
// Exact integer phase reduction since L = 8192 = 2^13.
// ---------------------------------------------------------------------------
__global__ void __launch_bounds__(256) k_trig()
{
    int idx = blockIdx.x * 256 + threadIdx.x;
    if (idx >= (TQ + 1) * MODES) return;
    int t = idx >> 4, k = idx & 15;
    int m = (t * k) & (LL - 1);
    float ang = (float)m * 7.6699039394282058e-4f;  // 2*pi/8192
    float s, c;
    sincosf(ang, &s, &c);
    g_C[t * JJ + 2 * k]     = c;
    g_C[t * JJ + 2 * k + 1] = s;
}

// ---------------------------------------------------------------------------
// K4: fused main with DIF butterfly symmetry.
//   Pce/Pco = even/odd-k cos partials, Pse/Pso = even/odd-k sin partials
//   x(t)       = (Pce+Pco) + (Pse+Pso)
//   x(4096+t)  = (Pce-Pco) + (Pse-Pso)
//   x(4096-t)  = (Pce-Pco) - (Pse-Pso)
//   x(8192-t)  = (Pce+Pco) - (Pse+Pso)
// One warp iteration handles 2 base-t values => 8 outputs sharing G-row loads.
// ---------------------------------------------------------------------------
__global__ void __launch_bounds__(256) k_main(
    const float* __restrict__ b1, const float* __restrict__ w2,
    const float* __restrict__ b2, float* __restrict__ out)
{
    __shared__ float4 Gs[JJ * 32];   // row j, lane = column group, 16KB
    const int tid = threadIdx.x;
    const int b = blockIdx.y;
    const float4* Gg = reinterpret_cast<const float4*>(g_G + b * JJ * N1);
    for (int i = tid; i < JJ * 32; i += 256) Gs[i] = Gg[i];
    __syncthreads();

    const int lane = tid & 31, warp = tid >> 5;
    const float4 b1v = reinterpret_cast<const float4*>(b1)[lane];
    const float4 w2v = reinterpret_cast<const float4*>(w2)[lane];
    const float bias2 = b2[0];
    float* outb = out + b * LOUT;

    const int wstride = gridDim.x * 8;
    for (int p = blockIdx.x * 8 + warp; p <= TQ / 2; p += wstride) {
        const int t1 = 2 * p;
        const int t2 = 2 * p + 1;
        const bool v2 = (t2 <= TQ);
        const int t2c = v2 ? t2 : t1;          // clamp (value unused when !v2)
        float cv1 = g_C[t1 * JJ + lane];
        float cv2 = g_C[t2c * JJ + lane];

        float4 z = make_float4(0.f, 0.f, 0.f, 0.f);
        float4 Pce1 = z, Pco1 = z, Pse1 = z, Pso1 = z;
        float4 Pce2 = z, Pco2 = z, Pse2 = z, Pso2 = z;

#pragma unroll
        for (int k = 0; k < MODES; k++) {
            float4 A = Gs[(2 * k) * 32 + lane];
            float4 B = Gs[(2 * k + 1) * 32 + lane];
            float c1 = __shfl_sync(0xffffffffu, cv1, 2 * k);
            float s1 = __shfl_sync(0xffffffffu, cv1, 2 * k + 1);
            float c2 = __shfl_sync(0xffffffffu, cv2, 2 * k);
            float s2 = __shfl_sync(0xffffffffu, cv2, 2 * k + 1);
            if (k & 1) {
                Pco1 = f4fma(c1, A, Pco1); Pso1 = f4fma(s1, B, Pso1);
                Pco2 = f4fma(c2, A, Pco2); Pso2 = f4fma(s2, B, Pso2);
            } else {
                Pce1 = f4fma(c1, A, Pce1); Pse1 = f4fma(s1, B, Pse1);
                Pce2 = f4fma(c2, A, Pce2); Pse2 = f4fma(s2, B, Pse2);
            }
        }

#pragma unroll
        for (int g = 0; g < 2; g++) {
            if (g == 1 && !v2) break;
            float4 Pce = g ? Pce2 : Pce1, Pco = g ? Pco2 : Pco1;
            float4 Pse = g ? Pse2 : Pse1, Pso = g ? Pso2 : Pso1;
            int t = g ? t2 : t1;

            float4 Ce = f4add(Pce, Pco), Cd = f4sub(Pce, Pco);
            float4 Se = f4add(Pse, Pso), Sd = f4sub(Pse, Pso);

            float4 accs[4];
            accs[0] = f4add(b1v, f4add(Ce, Se));   // t
            accs[1] = f4add(b1v, f4add(Cd, Sd));   // 4096+t
            accs[2] = f4add(b1v, f4sub(Cd, Sd));   // 4096-t
            accs[3] = f4add(b1v, f4sub(Ce, Se));   // 8192-t
            int idxs[4] = {t, LL / 2 + t, LL / 2 - t, LL - t};

#pragma unroll
            for (int o = 0; o < 4; o++) {
                float4 a = accs[o];
                float h0 = gelu1(a.x), h1 = gelu1(a.y);
                float h2 = gelu1(a.z), h3 = gelu1(a.w);
                float part = fmaf(h0, w2v.x,
                             fmaf(h1, w2v.y,
                             fmaf(h2, w2v.z, h3 * w2v.w)));
#pragma unroll
                for (int off = 16; off; off >>= 1)
                    part += __shfl_xor_sync(0xffffffffu, part, off);
                if (lane == 0 && idxs[o] < LOUT)
                    outb[idxs[o]] = part + bias2;
            }
        }
    }
}

// ---------------------------------------------------------------------------
extern "C" void kernel_launch(void* const* d_in, const int* in_sizes, int n_in,
                              void* d_out, int out_size)
{
    int i = 1;
    if (n_in >= 8 && in_sizes[1] == 1) i = 2;  // skip x_len if present
    const float* token = (const float*)d_in[0];
    const float* w_dec = (const float*)d_in[i];
    const float* b_dec = (const float*)d_in[i + 1];
    const float* w1    = (const float*)d_in[i + 2];
    const float* b1    = (const float*)d_in[i + 3];
    const float* w2    = (const float*)d_in[i + 4];
    const float* b2    = (const float*)d_in[i + 5];
    float* out = (float*)d_out;

    k_decode<<<dim3(CDEC / 128, BB / 8), 128>>>(token, w_dec, b_dec);
    k_fusemat<<<BB, 256>>>(w1);
    k_trig<<<((TQ + 1) * MODES + 255) / 256, 256>>>();
    k_main<<<dim3(16, BB), 256>>>(b1, w2, b2, out);
}

// round 8
// speedup vs baseline: 2.6518x; 1.2149x over previous
#include <cuda_runtime.h>
#include <math.h>

#define BB     64
#define EMB    1024
#define CDEC   2048     // WIDTH*MODES*2
#define WID    64
#define MODES  16
#define JJ     32       // 2*MODES
#define LL     8192
#define LOUT   8190
#define N1     128
#define TQ     2048     // base t range [0, 2048]; mirrors cover the rest

// device scratch (no allocations allowed)
__device__ float g_M[BB * JJ * WID];       // [b][j][w] scaled mode coeffs
__device__ float g_G[BB * JJ * N1];        // [b][j][n] = M[b] @ w1
__device__ float g_C[(TQ + 2) * JJ];       // [t][j] trig for t in [0,2048]
__device__ int   g_unsafe;                 // 1 if |preact| may exceed poly range

// ---------------------------------------------------------------------------
// float4 helpers
// ---------------------------------------------------------------------------
__device__ __forceinline__ float4 f4add(float4 a, float4 b) {
    return make_float4(a.x + b.x, a.y + b.y, a.z + b.z, a.w + b.w);
}
__device__ __forceinline__ float4 f4sub(float4 a, float4 b) {
    return make_float4(a.x - b.x, a.y - b.y, a.z - b.z, a.w - b.w);
}
__device__ __forceinline__ float4 f4fma(float s, float4 a, float4 acc) {
    return make_float4(fmaf(s, a.x, acc.x), fmaf(s, a.y, acc.y),
                       fmaf(s, a.z, acc.z), fmaf(s, a.w, acc.w));
}
// exact gelu (fallback)
__device__ __forceinline__ float gelu_exact(float x) {
    return 0.5f * x * (1.f + erff(x * 0.70710678118654752f));
}
// polynomial gelu: x * Phi(x), Phi = 0.5 + x*Q(x^2), odd Taylor through x^9.
// abs error < 5e-9 for |x| <= 0.5 (guarded by g_unsafe bound check).
__device__ __forceinline__ float gelu_poly(float x) {
    const float c0 =  0.3989422804014327f;
    const float c1 = -0.06649038006690545f;
    const float c2 =  0.009973557010035817f;
    const float c3 = -1.1873282154803355e-3f;
    const float c4 =  1.154347419510629e-4f;
    float t = x * x;
    float q = fmaf(fmaf(fmaf(fmaf(c4, t, c3), t, c2), t, c1), t, c0);
    return x * fmaf(x, q, 0.5f);
}

// ---------------------------------------------------------------------------
// K1: h = token @ w_dec + b_dec, scaled directly into M[b][j][w].
// Also resets g_unsafe (stream order guarantees visibility to K2).
// ---------------------------------------------------------------------------
__global__ void __launch_bounds__(128) k_decode(
    const float* __restrict__ token, const float* __restrict__ w_dec,
    const float* __restrict__ b_dec)
{
    __shared__ float tok[8 * EMB];   // [p][bb], 32KB
    const int tx = threadIdx.x;
    const int b0 = blockIdx.y * 8;
    const int c  = blockIdx.x * 128 + tx;

    if (blockIdx.x == 0 && blockIdx.y == 0 && tx == 0) g_unsafe = 0;

    for (int i = tx; i < 8 * EMB; i += 128) {
        int bb = i >> 10, p = i & 1023;
        tok[p * 8 + bb] = token[(b0 + bb) * EMB + p];
    }
    __syncthreads();

    float acc0 = 0.f, acc1 = 0.f, acc2 = 0.f, acc3 = 0.f;
    float acc4 = 0.f, acc5 = 0.f, acc6 = 0.f, acc7 = 0.f;
#pragma unroll 4
    for (int p = 0; p < EMB; p++) {
        float wv = w_dec[p * CDEC + c];
        float4 t0 = *reinterpret_cast<const float4*>(&tok[p * 8]);
        float4 t1 = *reinterpret_cast<const float4*>(&tok[p * 8 + 4]);
        acc0 = fmaf(t0.x, wv, acc0); acc1 = fmaf(t0.y, wv, acc1);
        acc2 = fmaf(t0.z, wv, acc2); acc3 = fmaf(t0.w, wv, acc3);
        acc4 = fmaf(t1.x, wv, acc4); acc5 = fmaf(t1.y, wv, acc5);
        acc6 = fmaf(t1.z, wv, acc6); acc7 = fmaf(t1.w, wv, acc7);
    }
    float bd = b_dec[c];
    int w = c >> 5, j = c & 31;
    // irfft coefficients: DC cos = 1/L, Im(X0) ignored; k>=1: 2*Re/L, -2*Im/L
    float sc;
    if (j == 0)      sc = 1.0f / (float)LL;
    else if (j == 1) sc = 0.0f;
    else             sc = (j & 1) ? (-2.0f / (float)LL) : (2.0f / (float)LL);

    float a[8] = {acc0, acc1, acc2, acc3, acc4, acc5, acc6, acc7};
#pragma unroll
    for (int bb = 0; bb < 8; bb++)
        g_M[(b0 + bb) * (JJ * WID) + j * WID + w] = sc * (a[bb] + bd);
}

// ---------------------------------------------------------------------------
// K2: G[b] = M[b] (32x64) @ w1 (64x128). One block per b.
// Also computes the rigorous preact bound: max_n (sum_j |G[j][n]| + |b1[n]|);
// flags g_unsafe if it could exceed the poly-gelu validity range.
// ---------------------------------------------------------------------------
__global__ void __launch_bounds__(256) k_fusemat(
    const float* __restrict__ w1, const float* __restrict__ b1)
{
    __shared__ float Ms[JJ * WID];
    __shared__ float W1s[WID * N1];
    const int tid = threadIdx.x;
    const int b = blockIdx.x;
    for (int i = tid; i < JJ * WID; i += 256) Ms[i] = g_M[b * JJ * WID + i];
    for (int i = tid; i < WID * N1; i += 256) W1s[i] = w1[i];
    __syncthreads();
    for (int idx = tid; idx < JJ * N1; idx += 256) {
        int j = idx >> 7, n = idx & 127;
        float acc = 0.f;
#pragma unroll 8
        for (int p = 0; p < WID; p++)
            acc = fmaf(Ms[j * WID + p], W1s[p * N1 + n], acc);
        g_G[b * JJ * N1 + idx] = acc;
    }
    __syncthreads();
    if (tid < N1) {
        float s = fabsf(b1[tid]);
#pragma unroll 8
        for (int j = 0; j < JJ; j++)
            s += fabsf(g_G[b * JJ * N1 + j * N1 + tid]);
        if (s > 0.45f) g_unsafe = 1;
    }
}

// ---------------------------------------------------------------------------
// K3: trig table for base t in [0, 2048] only (symmetry covers the rest).
// Exact integer phase reduction since L = 8192 = 2^13.
// ---------------------------------------------------------------------------
__global__ void __launch_bounds__(256) k_trig()
{
    int idx = blockIdx.x * 256 + threadIdx.x;
    if (idx >= (TQ + 1) * MODES) return;
    int t = idx >> 4, k = idx & 15;
    int m = (t * k) & (LL - 1);
    float ang = (float)m * 7.6699039394282058e-4f;  // 2*pi/8192
    float s, c;
    sincosf(ang, &s, &c);
    g_C[t * JJ + 2 * k]     = c;
    g_C[t * JJ + 2 * k + 1] = s;
}

// ---------------------------------------------------------------------------
// K4: fused main with DIF butterfly symmetry + polynomial gelu.
//   Pce/Pco = even/odd-k cos partials, Pse/Pso = even/odd-k sin partials
//   x(t)       = (Pce+Pco) + (Pse+Pso)
//   x(4096+t)  = (Pce-Pco) + (Pse-Pso)
//   x(4096-t)  = (Pce-Pco) - (Pse-Pso)
//   x(8192-t)  = (Pce+Pco) - (Pse+Pso)
// Grid sized for a single wave (3 blocks/SM via launch_bounds, 384 blocks).
// ---------------------------------------------------------------------------
__global__ void __launch_bounds__(256, 3) k_main(
    const float* __restrict__ b1, const float* __restrict__ w2,
    const float* __restrict__ b2, float* __restrict__ out)
{
    __shared__ float4 Gs[JJ * 32];   // row j, lane = column group, 16KB
    const int tid = threadIdx.x;
    const int b = blockIdx.y;
    const float4* Gg = reinterpret_cast<const float4*>(g_G + b * JJ * N1);
    for (int i = tid; i < JJ * 32; i += 256) Gs[i] = Gg[i];
    __syncthreads();

    const int lane = tid & 31, warp = tid >> 5;
    const float4 b1v = reinterpret_cast<const float4*>(b1)[lane];
    const float4 w2v = reinterpret_cast<const float4*>(w2)[lane];
    const float bias2 = b2[0];
    const int unsafe = g_unsafe;     // uniform
    float* outb = out + b * LOUT;

    const int wstride = gridDim.x * 8;
    for (int p = blockIdx.x * 8 + warp; p <= TQ / 2; p += wstride) {
        const int t1 = 2 * p;
        const int t2 = 2 * p + 1;
        const bool v2 = (t2 <= TQ);
        const int t2c = v2 ? t2 : t1;
        float cv1 = g_C[t1 * JJ + lane];
        float cv2 = g_C[t2c * JJ + lane];

        float4 z = make_float4(0.f, 0.f, 0.f, 0.f);
        float4 Pce1 = z, Pco1 = z, Pse1 = z, Pso1 = z;
        float4 Pce2 = z, Pco2 = z, Pse2 = z, Pso2 = z;

#pragma unroll
        for (int k = 0; k < MODES; k++) {
            float4 A = Gs[(2 * k) * 32 + lane];
            float4 B = Gs[(2 * k + 1) * 32 + lane];
            float c1 = __shfl_sync(0xffffffffu, cv1, 2 * k);
            float s1 = __shfl_sync(0xffffffffu, cv1, 2 * k + 1);
            float c2 = __shfl_sync(0xffffffffu, cv2, 2 * k);
            float s2 = __shfl_sync(0xffffffffu, cv2, 2 * k + 1);
            if (k & 1) {
                Pco1 = f4fma(c1, A, Pco1); Pso1 = f4fma(s1, B, Pso1);
                Pco2 = f4fma(c2, A, Pco2); Pso2 = f4fma(s2, B, Pso2);
            } else {
                Pce1 = f4fma(c1, A, Pce1); Pse1 = f4fma(s1, B, Pse1);
                Pce2 = f4fma(c2, A, Pce2); Pse2 = f4fma(s2, B, Pse2);
            }
        }

#pragma unroll
        for (int g = 0; g < 2; g++) {
            if (g == 1 && !v2) break;
            float4 Pce = g ? Pce2 : Pce1, Pco = g ? Pco2 : Pco1;
            float4 Pse = g ? Pse2 : Pse1, Pso = g ? Pso2 : Pso1;
            int t = g ? t2 : t1;

            // fold b1 into cos terms (saves 8 FADD/group)
            float4 Ceb = f4add(f4add(Pce, Pco), b1v);
            float4 Cdb = f4add(f4sub(Pce, Pco), b1v);
            float4 Se  = f4add(Pse, Pso), Sd = f4sub(Pse, Pso);

            float4 accs[4];
            accs[0] = f4add(Ceb, Se);   // t
            accs[1] = f4add(Cdb, Sd);   // 4096+t
            accs[2] = f4sub(Cdb, Sd);   // 4096-t
            accs[3] = f4sub(Ceb, Se);   // 8192-t
            int idxs[4] = {t, LL / 2 + t, LL / 2 - t, LL - t};

#pragma unroll
            for (int o = 0; o < 4; o++) {
                float4 a = accs[o];
                float h0, h1, h2, h3;
                if (!unsafe) {
                    h0 = gelu_poly(a.x); h1 = gelu_poly(a.y);
                    h2 = gelu_poly(a.z); h3 = gelu_poly(a.w);
                } else {
                    h0 = gelu_exact(a.x); h1 = gelu_exact(a.y);
                    h2 = gelu_exact(a.z); h3 = gelu_exact(a.w);
                }
                float part = fmaf(h0, w2v.x,
                             fmaf(h1, w2v.y,
                             fmaf(h2, w2v.z, h3 * w2v.w)));
#pragma unroll
                for (int off = 16; off; off >>= 1)
                    part += __shfl_xor_sync(0xffffffffu, part, off);
                if (lane == 0 && idxs[o] < LOUT)
                    outb[idxs[o]] = part + bias2;
            }
        }
    }
}

// ---------------------------------------------------------------------------
extern "C" void kernel_launch(void* const* d_in, const int* in_sizes, int n_in,
                              void* d_out, int out_size)
{
    int i = 1;
    if (n_in >= 8 && in_sizes[1] == 1) i = 2;  // skip x_len if present
    const float* token = (const float*)d_in[0];
    const float* w_dec = (const float*)d_in[i];
    const float* b_dec = (const float*)d_in[i + 1];
    const float* w1    = (const float*)d_in[i + 2];
    const float* b1    = (const float*)d_in[i + 3];
    const float* w2    = (const float*)d_in[i + 4];
    const float* b2    = (const float*)d_in[i + 5];
    float* out = (float*)d_out;

    k_decode<<<dim3(CDEC / 128, BB / 8), 128>>>(token, w_dec, b_dec);
    k_fusemat<<<BB, 256>>>(w1, b1);
    k_trig<<<((TQ + 1) * MODES + 255) / 256, 256>>>();
    // single wave: 6*64 = 384 blocks, 3 blocks/SM (enforced by launch_bounds)
    k_main<<<dim3(6, BB), 256>>>(b1, w2, b2, out);
}

// round 9
// speedup vs baseline: 2.7289x; 1.0291x over previous
#include <cuda_runtime.h>
#include <math.h>

#define BB     64
#define EMB    1024
#define CDEC   2048     // WIDTH*MODES*2
#define WID    64
#define MODES  16
#define JJ     32       // 2*MODES
#define LL     8192
#define LOUT   8190
#define N1     128
#define TQ     2048     // base t range [0, 2048]; mirrors cover the rest
#define NP     1025     // p values per batch (p = 0..1024)
#define NTASK  (BB * NP)
#define NBLK   444      // 3 blocks/SM * 148 SMs = exactly one wave

// device scratch (no allocations allowed)
__device__ float g_M[BB * JJ * WID];        // [b][j][w] scaled mode coeffs
__device__ float2 g_G2[BB * MODES * N1];    // [b][k][n] = (cosRow G[2k][n], sinRow G[2k+1][n])
__device__ float g_C[(TQ + 2) * JJ];        // [t][4κ..] = (c_{2κ}, s_{2κ}, c_{2κ+1}, s_{2κ+1})
__device__ int   g_unsafe;                  // 1 if |preact| may exceed poly range

// ---------------------------------------------------------------------------
// packed f32x2 helpers (sm_103a): explicit PTX, ptxas won't auto-fuse
// ---------------------------------------------------------------------------
typedef unsigned long long u64;
__device__ __forceinline__ u64 pk2(float x, float y) {
    u64 r; asm("mov.b64 %0, {%1, %2};" : "=l"(r) : "f"(x), "f"(y)); return r;
}
__device__ __forceinline__ float2 upk(u64 v) {
    float2 r; asm("mov.b64 {%0, %1}, %2;" : "=f"(r.x), "=f"(r.y) : "l"(v)); return r;
}
__device__ __forceinline__ u64 pfma(u64 a, u64 b, u64 c) {
    u64 d; asm("fma.rn.f32x2 %0, %1, %2, %3;" : "=l"(d) : "l"(a), "l"(b), "l"(c)); return d;
}
__device__ __forceinline__ u64 padd(u64 a, u64 b) {
    u64 d; asm("add.rn.f32x2 %0, %1, %2;" : "=l"(d) : "l"(a), "l"(b)); return d;
}
__device__ __forceinline__ u64 pmul(u64 a, u64 b) {
    u64 d; asm("mul.rn.f32x2 %0, %1, %2;" : "=l"(d) : "l"(a), "l"(b)); return d;
}
__device__ __forceinline__ float gelu_exact(float x) {
    return 0.5f * x * (1.f + erff(x * 0.70710678118654752f));
}

// ---------------------------------------------------------------------------
// K1: h = token @ w_dec + b_dec -> scaled M[b][j][w].
// 4 batches/block, grid (16,16)=256 blocks: enough warps to hide L2 latency.
// ---------------------------------------------------------------------------
__global__ void __launch_bounds__(128) k_decode(
    const float* __restrict__ token, const float* __restrict__ w_dec,
    const float* __restrict__ b_dec)
{
    __shared__ float tok[4 * EMB];   // [p][bb], 16KB
    const int tx = threadIdx.x;
    const int b0 = blockIdx.y * 4;
    const int c  = blockIdx.x * 128 + tx;

    if (blockIdx.x == 0 && blockIdx.y == 0 && tx == 0) g_unsafe = 0;

    for (int i = tx; i < 4 * EMB; i += 128) {
        int bb = i >> 10, p = i & 1023;
        tok[p * 4 + bb] = token[(b0 + bb) * EMB + p];
    }
    __syncthreads();

    float a0 = 0.f, a1 = 0.f, a2 = 0.f, a3 = 0.f;
#pragma unroll 8
    for (int p = 0; p < EMB; p++) {
        float wv = w_dec[p * CDEC + c];
        float4 t = *reinterpret_cast<const float4*>(&tok[p * 4]);
        a0 = fmaf(t.x, wv, a0); a1 = fmaf(t.y, wv, a1);
        a2 = fmaf(t.z, wv, a2); a3 = fmaf(t.w, wv, a3);
    }
    float bd = b_dec[c];
    int w = c >> 5, j = c & 31;
    float sc;
    if (j == 0)      sc = 1.0f / (float)LL;
    else if (j == 1) sc = 0.0f;
    else             sc = (j & 1) ? (-2.0f / (float)LL) : (2.0f / (float)LL);

    float a[4] = {a0, a1, a2, a3};
#pragma unroll
    for (int bb = 0; bb < 4; bb++)
        g_M[(b0 + bb) * (JJ * WID) + j * WID + w] = sc * (a[bb] + bd);
}

// ---------------------------------------------------------------------------
// K2: G[b] = M[b] (32x64) @ w1 (64x128), written INTERLEAVED:
//   g_G2[b][k][n] = (G[2k][n], G[2k+1][n]).
// Plus rigorous preact bound -> g_unsafe.
// ---------------------------------------------------------------------------
__global__ void __launch_bounds__(256) k_fusemat(
    const float* __restrict__ w1, const float* __restrict__ b1)
{
    __shared__ float Ms[JJ * WID];
    __shared__ float W1s[WID * N1];
    const int tid = threadIdx.x;
    const int b = blockIdx.x;
    for (int i = tid; i < JJ * WID; i += 256) Ms[i] = g_M[b * JJ * WID + i];
    for (int i = tid; i < WID * N1; i += 256) W1s[i] = w1[i];
    __syncthreads();
    float* gf = reinterpret_cast<float*>(g_G2 + b * MODES * N1);
    for (int idx = tid; idx < JJ * N1; idx += 256) {
        int j = idx >> 7, n = idx & 127;
        float acc = 0.f;
#pragma unroll 8
        for (int p = 0; p < WID; p++)
            acc = fmaf(Ms[j * WID + p], W1s[p * N1 + n], acc);
        int k = j >> 1, comp = j & 1;
        gf[(k * N1 + n) * 2 + comp] = acc;
    }
    __syncthreads();
    if (tid < N1) {
        float s = fabsf(b1[tid]);
#pragma unroll 8
        for (int k = 0; k < MODES; k++) {
            float2 v = g_G2[b * MODES * N1 + k * N1 + tid];
            s += fabsf(v.x) + fabsf(v.y);
        }
        if (s > 0.45f) g_unsafe = 1;
    }
}

// ---------------------------------------------------------------------------
// K3: trig table for t in [0, 2048]; exact integer phase reduction (L=2^13).
// ---------------------------------------------------------------------------
__global__ void __launch_bounds__(256) k_trig()
{
    int idx = blockIdx.x * 256 + threadIdx.x;
    if (idx >= (TQ + 1) * MODES) return;
    int t = idx >> 4, k = idx & 15;
    int m = (t * k) & (LL - 1);
    float ang = (float)m * 7.6699039394282058e-4f;  // 2*pi/8192
    float s, c;
    sincosf(ang, &s, &c);
    g_C[t * JJ + 2 * k]     = c;
    g_C[t * JJ + 2 * k + 1] = s;
}

// ---------------------------------------------------------------------------
// K4: fused main. Packed f32x2 accumulation; trig via warp-uniform __ldg
// (broadcast) -> zero broadcast shfls. Flat task space over (b, p) mapped to
// exactly 444 blocks (one full wave, 3/SM). Each block's contiguous range
// spans <= 2 consecutive b; both G2 tiles staged in smem.
// Accumulator halves: Pe[n] = (even-mode cos partial, even-mode sin partial).
//   U = Pe+Po = (Ce, Se); V = Pe-Po = (Cd, Sd)
//   x(t)=Ce+Se, x(4096+t)=Cd+Sd, x(4096-t)=Cd-Sd, x(8192-t)=Ce-Se (+b1 each)
// ---------------------------------------------------------------------------
__global__ void __launch_bounds__(256, 3) k_main(
    const float* __restrict__ b1, const float* __restrict__ w2,
    const float* __restrict__ b2, float* __restrict__ out)
{
    __shared__ u64 Gs[2 * MODES * N1];   // 2 tiles x 16KB
    const int tid = threadIdx.x;
    const int lane = tid & 31, warp = tid >> 5;

    const int start = (int)(((long long)blockIdx.x * NTASK) / NBLK);
    const int end   = (int)(((long long)(blockIdx.x + 1) * NTASK) / NBLK);
    const int b0 = start / NP;
    const int b1i = (b0 + 1 < BB) ? b0 + 1 : b0;

    const u64* G2g0 = reinterpret_cast<const u64*>(g_G2 + b0 * MODES * N1);
    const u64* G2g1 = reinterpret_cast<const u64*>(g_G2 + b1i * MODES * N1);
    for (int i = tid; i < MODES * N1; i += 256) {
        Gs[i] = G2g0[i];
        Gs[MODES * N1 + i] = G2g1[i];
    }
    __syncthreads();

    const float4 b1v = reinterpret_cast<const float4*>(b1)[lane];
    const float4 w2v = reinterpret_cast<const float4*>(w2)[lane];
    const u64 w2_01 = pk2(w2v.x, w2v.y), w2_23 = pk2(w2v.z, w2v.w);
    const float bias2 = b2[0];
    const int unsafe = g_unsafe;

    // packed gelu-poly constants (odd Taylor of x*Phi(x) through x^9,
    // |err| < 5e-9 on |x|<=0.5, guarded by g_unsafe)
    const u64 pc0 = pk2( 0.3989422804014327f,    0.3989422804014327f);
    const u64 pc1 = pk2(-0.06649038006690545f,  -0.06649038006690545f);
    const u64 pc2 = pk2( 0.009973557010035817f,  0.009973557010035817f);
    const u64 pc3 = pk2(-1.1873282154803355e-3f,-1.1873282154803355e-3f);
    const u64 pc4 = pk2( 1.154347419510629e-4f,  1.154347419510629e-4f);
    const u64 phalf = pk2(0.5f, 0.5f);

    for (int tau = start + warp; tau < end; tau += 8) {
        const int b = tau / NP;
        const int p = tau - b * NP;
        const int t1 = 2 * p;
        const int t2 = 2 * p + 1;
        const bool v2 = (t2 <= TQ);
        const int t2c = v2 ? t2 : t1;
        const u64* G = Gs + (b - b0) * (MODES * N1);
        float* outb = out + b * LOUT;

        const float4* C1 = reinterpret_cast<const float4*>(g_C + t1 * JJ);
        const float4* C2 = reinterpret_cast<const float4*>(g_C + t2c * JJ);

        u64 Pe1[4] = {0, 0, 0, 0}, Po1[4] = {0, 0, 0, 0};
        u64 Pe2[4] = {0, 0, 0, 0}, Po2[4] = {0, 0, 0, 0};

#pragma unroll
        for (int kk = 0; kk < 8; kk++) {
            // warp-uniform trig loads (broadcast): (c_{2kk}, s_{2kk}, c_{2kk+1}, s_{2kk+1})
            float4 q1 = __ldg(&C1[kk]);
            float4 q2 = __ldg(&C2[kk]);
            u64 cs1e = pk2(q1.x, q1.y), cs1o = pk2(q1.z, q1.w);
            u64 cs2e = pk2(q2.x, q2.y), cs2o = pk2(q2.z, q2.w);

            const ulonglong2* re = reinterpret_cast<const ulonglong2*>(
                G + (2 * kk) * N1 + 4 * lane);
            const ulonglong2* ro = reinterpret_cast<const ulonglong2*>(
                G + (2 * kk + 1) * N1 + 4 * lane);
            ulonglong2 ea = re[0], eb = re[1];
            ulonglong2 oa = ro[0], ob = ro[1];

            Pe1[0] = pfma(cs1e, ea.x, Pe1[0]); Pe1[1] = pfma(cs1e, ea.y, Pe1[1]);
            Pe1[2] = pfma(cs1e, eb.x, Pe1[2]); Pe1[3] = pfma(cs1e, eb.y, Pe1[3]);
            Po1[0] = pfma(cs1o, oa.x, Po1[0]); Po1[1] = pfma(cs1o, oa.y, Po1[1]);
            Po1[2] = pfma(cs1o, ob.x, Po1[2]); Po1[3] = pfma(cs1o, ob.y, Po1[3]);

            Pe2[0] = pfma(cs2e, ea.x, Pe2[0]); Pe2[1] = pfma(cs2e, ea.y, Pe2[1]);
            Pe2[2] = pfma(cs2e, eb.x, Pe2[2]); Pe2[3] = pfma(cs2e, eb.y, Pe2[3]);
            Po2[0] = pfma(cs2o, oa.x, Po2[0]); Po2[1] = pfma(cs2o, oa.y, Po2[1]);
            Po2[2] = pfma(cs2o, ob.x, Po2[2]); Po2[3] = pfma(cs2o, ob.y, Po2[3]);
        }

        const float b1a[4] = {b1v.x, b1v.y, b1v.z, b1v.w};

#pragma unroll
        for (int g = 0; g < 2; g++) {
            if (g == 1 && !v2) break;
            const u64* Pe = g ? Pe2 : Pe1;
            const u64* Po = g ? Po2 : Po1;
            const int t = g ? t2 : t1;

            float xt[4], xu[4], xv[4], xw[4];
#pragma unroll
            for (int j = 0; j < 4; j++) {
                float2 Uf = upk(padd(Pe[j], Po[j]));   // (Ce, Se)
                float2 Pef = upk(Pe[j]);
                float2 Pof = upk(Po[j]);
                float Vlo = Pef.x - Pof.x;             // Cd
                float Vhi = Pef.y - Pof.y;             // Sd
                float a0 = Uf.x + b1a[j];
                xt[j] = a0 + Uf.y;                     // x(t)
                xw[j] = a0 - Uf.y;                     // x(8192-t)
                float c0 = Vlo + b1a[j];
                xu[j] = c0 + Vhi;                      // x(4096+t)
                xv[j] = c0 - Vhi;                      // x(4096-t)
            }

            const float* Xs[4] = {xt, xu, xv, xw};
            const int idxs[4] = {t, LL / 2 + t, LL / 2 - t, LL - t};

#pragma unroll
            for (int o = 0; o < 4; o++) {
                const float* X = Xs[o];
                float part;
                if (!unsafe) {
                    u64 x01 = pk2(X[0], X[1]), x23 = pk2(X[2], X[3]);
                    u64 t01 = pmul(x01, x01), t23 = pmul(x23, x23);
                    u64 q01 = pfma(pfma(pfma(pfma(pc4, t01, pc3), t01, pc2), t01, pc1), t01, pc0);
                    u64 q23 = pfma(pfma(pfma(pfma(pc4, t23, pc3), t23, pc2), t23, pc1), t23, pc0);
                    u64 h01 = pmul(x01, pfma(x01, q01, phalf));
                    u64 h23 = pmul(x23, pfma(x23, q23, phalf));
                    u64 d = pfma(h23, w2_23, pmul(h01, w2_01));
                    float2 df = upk(d);
                    part = df.x + df.y;
                } else {
                    float h0 = gelu_exact(X[0]), h1 = gelu_exact(X[1]);
                    float h2 = gelu_exact(X[2]), h3 = gelu_exact(X[3]);
                    part = fmaf(h0, w2v.x, fmaf(h1, w2v.y,
                           fmaf(h2, w2v.z, h3 * w2v.w)));
                }
#pragma unroll
                for (int off = 16; off; off >>= 1)
                    part += __shfl_xor_sync(0xffffffffu, part, off);
                if (lane == 0 && idxs[o] < LOUT)
                    outb[idxs[o]] = part + bias2;
            }
        }
    }
}

// ---------------------------------------------------------------------------
extern "C" void kernel_launch(void* const* d_in, const int* in_sizes, int n_in,
                              void* d_out, int out_size)
{
    int i = 1;
    if (n_in >= 8 && in_sizes[1] == 1) i = 2;  // skip x_len if present
    const float* token = (const float*)d_in[0];
    const float* w_dec = (const float*)d_in[i];
    const float* b_dec = (const float*)d_in[i + 1];
    const float* w1    = (const float*)d_in[i + 2];
    const float* b1    = (const float*)d_in[i + 3];
    const float* w2    = (const float*)d_in[i + 4];
    const float* b2    = (const float*)d_in[i + 5];
    float* out = (float*)d_out;

    k_decode<<<dim3(CDEC / 128, BB / 4), 128>>>(token, w_dec, b_dec);
    k_fusemat<<<BB, 256>>>(w1, b1);
    k_trig<<<((TQ + 1) * MODES + 255) / 256, 256>>>();
    k_main<<<NBLK, 256>>>(b1, w2, b2, out);
}